// round 14
// baseline (speedup 1.0000x reference)
#include <cuda_runtime.h>
#include <cuda_bf16.h>
#include <cstdint>
#include <math.h>

// Problem constants
#define Bn  2
#define Sn  2048
#define Dn  2048
#define Hn  16
#define DHn 128
#define Mn  (Bn*Sn)          // 4096 rows for all GEMMs

// ---------------------------------------------------------------------------
// Scratch (no allocation allowed -> __device__ globals)
// ---------------------------------------------------------------------------
__device__ float g_ct[Sn*64];
__device__ float g_st[Sn*64];

// bf16 split copies
__device__ __nv_bfloat16 g_xh[(size_t)Mn*Dn],  g_xl[(size_t)Mn*Dn];   // x splits, later O splits
__device__ __nv_bfloat16 g_Vh[(size_t)Mn*Dn],  g_Vl[(size_t)Mn*Dn];
__device__ __nv_bfloat16 g_Qh[(size_t)Mn*Dn],  g_Ql[(size_t)Mn*Dn];
__device__ __nv_bfloat16 g_Kh[(size_t)Mn*Dn],  g_Kl[(size_t)Mn*Dn];
__device__ __nv_bfloat16 g_qwh[(size_t)Dn*Dn], g_qwl[(size_t)Dn*Dn];
__device__ __nv_bfloat16 g_kwh[(size_t)Dn*Dn], g_kwl[(size_t)Dn*Dn];
__device__ __nv_bfloat16 g_vwh[(size_t)Dn*Dn], g_vwl[(size_t)Dn*Dn];
__device__ __nv_bfloat16 g_owh[(size_t)Dn*Dn], g_owl[(size_t)Dn*Dn];

__device__ __forceinline__ uint32_t smem_u32(const void* p) {
    uint32_t a;
    asm("{ .reg .u64 t; cvta.to.shared.u64 t, %1; cvt.u32.u64 %0, t; }"
        : "=r"(a) : "l"(p));
    return a;
}

#define CP_ASYNC16(smem_addr, gptr) \
    asm volatile("cp.async.cg.shared.global [%0], [%1], 16;" \
                 :: "r"(smem_addr), "l"(gptr) : "memory")
#define CP_COMMIT()  asm volatile("cp.async.commit_group;" ::: "memory")
#define CP_WAIT1()   asm volatile("cp.async.wait_group 1;"  ::: "memory")
#define CP_WAIT0()   asm volatile("cp.async.wait_group 0;"  ::: "memory")

#define LDSM_X4(r0,r1,r2,r3, addr) \
    asm volatile("ldmatrix.sync.aligned.m8n8.x4.shared.b16 {%0,%1,%2,%3}, [%4];" \
        : "=r"(r0),"=r"(r1),"=r"(r2),"=r"(r3) : "r"(addr))
#define LDSM_X4T(r0,r1,r2,r3, addr) \
    asm volatile("ldmatrix.sync.aligned.m8n8.x4.trans.shared.b16 {%0,%1,%2,%3}, [%4];" \
        : "=r"(r0),"=r"(r1),"=r"(r2),"=r"(r3) : "r"(addr))
#define MMA16816(d, a0,a1,a2,a3, b0,b1) \
    asm volatile("mma.sync.aligned.m16n8k16.row.col.f32.bf16.bf16.f32 " \
        "{%0,%1,%2,%3}, {%4,%5,%6,%7}, {%8,%9}, {%0,%1,%2,%3};" \
        : "+f"((d)[0]),"+f"((d)[1]),"+f"((d)[2]),"+f"((d)[3]) \
        : "r"(a0),"r"(a1),"r"(a2),"r"(a3), "r"(b0),"r"(b1))

__device__ __forceinline__ float ex2f(float x) {
    float r;
    asm("ex2.approx.ftz.f32 %0, %1;" : "=f"(r) : "f"(x));
    return r;
}

__device__ __forceinline__ __nv_bfloat162 split_hi2(float a, float b) {
    __nv_bfloat162 t;
    t.x = __float2bfloat16(a);
    t.y = __float2bfloat16(b);
    return t;
}
__device__ __forceinline__ __nv_bfloat162 split_lo2(float a, float b,
                                                    __nv_bfloat162 h) {
    __nv_bfloat162 t;
    t.x = __float2bfloat16(a - __bfloat162float(h.x));
    t.y = __float2bfloat16(b - __bfloat162float(h.y));
    return t;
}

// ---------------------------------------------------------------------------
// bf16 split conversion: hi = bf16(v), lo = bf16(v - hi)
// ---------------------------------------------------------------------------
__global__ void split_bf16_kernel(const float* __restrict__ src,
                                  __nv_bfloat16* __restrict__ hi,
                                  __nv_bfloat16* __restrict__ lo, int n4)
{
    int i = blockIdx.x * blockDim.x + threadIdx.x;
    if (i >= n4) return;
    float4 v = ((const float4*)src)[i];
    __nv_bfloat162 h0 = split_hi2(v.x, v.y);
    __nv_bfloat162 h1 = split_hi2(v.z, v.w);
    ((__nv_bfloat162*)hi)[i*2]   = h0;
    ((__nv_bfloat162*)hi)[i*2+1] = h1;
    ((__nv_bfloat162*)lo)[i*2]   = split_lo2(v.x, v.y, h0);
    ((__nv_bfloat162*)lo)[i*2+1] = split_lo2(v.z, v.w, h1);
}

// 4-tensor fused split (weights): z-dim selects tensor
struct Split4Args {
    const float* src[4];
    __nv_bfloat16* hi[4];
    __nv_bfloat16* lo[4];
};
__global__ void split4_kernel(Split4Args a, int n4)
{
    int i = blockIdx.x * blockDim.x + threadIdx.x;
    if (i >= n4) return;
    const int z = blockIdx.y;
    const float* src = a.src[z];
    __nv_bfloat16* hi = a.hi[z];
    __nv_bfloat16* lo = a.lo[z];
    float4 v = ((const float4*)src)[i];
    __nv_bfloat162 h0 = split_hi2(v.x, v.y);
    __nv_bfloat162 h1 = split_hi2(v.z, v.w);
    ((__nv_bfloat162*)hi)[i*2]   = h0;
    ((__nv_bfloat162*)hi)[i*2+1] = h1;
    ((__nv_bfloat162*)lo)[i*2]   = split_lo2(v.x, v.y, h0);
    ((__nv_bfloat162*)lo)[i*2+1] = split_lo2(v.z, v.w, h1);
}

// ---------------------------------------------------------------------------
// RoPE cos/sin table
// ---------------------------------------------------------------------------
__global__ void rope_table_kernel()
{
    __shared__ double inv_sh;
    const int i = blockIdx.x;                       // 0..63
    const int s = blockIdx.y * 256 + threadIdx.x;   // 0..2047
    if (threadIdx.x == 0)
        inv_sh = exp((double)(-2 * i) * (9.210340371976182736 / 128.0));
    __syncthreads();
    double ang = (double)s * inv_sh;
    double k   = floor(ang * 0.15915494309189533577 + 0.5);  // 1/(2pi)
    double red = ang - k * 6.2831853071795864769;
    float rf = (float)red;
    g_ct[(s << 6) | i] = cosf(rf);
    g_st[(s << 6) | i] = sinf(rf);
}

// ---------------------------------------------------------------------------
// Split-bf16 GEMM, 128x128 tile, k0-grouped 3-pass structure (R10-proven).
// blockIdx.z selects the output head (merged QKV launch or single).
// mode 0: fp32 out. mode 1: bf16 hi/lo split out. mode 2: rope+scale+split.
// ---------------------------------------------------------------------------
#define GK       2048
#define NK0      64                // 64 chunks of BK=32
#define TILE_B   10240             // 128 rows * 80B
#define STAGE_B  (4*TILE_B)        // Ah|Al|Wh|Wl = 40960
#define GSTAGES  2
#define GEMM_SMEM (GSTAGES*STAGE_B)   // 81920

struct GemmArgs {
    const __nv_bfloat16* Wh[3];
    const __nv_bfloat16* Wl[3];
    const float* bias[3];
    float* C[3];
    __nv_bfloat16* Ch[3];
    __nv_bfloat16* Cl[3];
    float scale[3];
    int   mode[3];
};

__global__ __launch_bounds__(256, 2) void gemm_mma(
    const __nv_bfloat16* __restrict__ Ah, const __nv_bfloat16* __restrict__ Al,
    GemmArgs args)
{
    extern __shared__ __align__(16) char smem[];

    const int z = blockIdx.z;
    const __nv_bfloat16* __restrict__ Wh = args.Wh[z];
    const __nv_bfloat16* __restrict__ Wl = args.Wl[z];
    const float* __restrict__ bias = args.bias[z];
    float* C = args.C[z];
    __nv_bfloat16* Ch = args.Ch[z];
    __nv_bfloat16* Cl = args.Cl[z];
    const float scale = args.scale[z];
    const int mode = args.mode[z];

    const int tid = threadIdx.x;
    const int lid = tid & 31;
    const int wid = tid >> 5;
    const int wm  = wid & 1;
    const int wn  = wid >> 1;
    const int bn  = blockIdx.x * 128;
    const int bm  = blockIdx.y * 128;
    const uint32_t sb = smem_u32(smem);

    const int gr = tid >> 2;
    const int gc = (tid & 3) * 8;

    const uint32_t sP0 = sb + (uint32_t)(gr * 80 + gc * 2);   // row slot in a tile

    float acc[4][4][4];
#pragma unroll
    for (int a = 0; a < 4; a++)
#pragma unroll
        for (int b = 0; b < 4; b++)
#pragma unroll
            for (int c = 0; c < 4; c++) acc[a][b][c] = 0.f;

    auto issue = [&](int ci) {
        const int k0 = ci << 5;
        const uint32_t off = (uint32_t)(ci & 1) * STAGE_B;
        CP_ASYNC16(sP0 + off,                     Ah + (size_t)(bm + gr)      * GK + k0 + gc);
        CP_ASYNC16(sP0 + off + 64*80,             Ah + (size_t)(bm + gr + 64) * GK + k0 + gc);
        CP_ASYNC16(sP0 + off + TILE_B,            Al + (size_t)(bm + gr)      * GK + k0 + gc);
        CP_ASYNC16(sP0 + off + TILE_B + 64*80,    Al + (size_t)(bm + gr + 64) * GK + k0 + gc);
        CP_ASYNC16(sP0 + off + 2*TILE_B,          Wh + (size_t)(bn + gr)      * GK + k0 + gc);
        CP_ASYNC16(sP0 + off + 2*TILE_B + 64*80,  Wh + (size_t)(bn + gr + 64) * GK + k0 + gc);
        CP_ASYNC16(sP0 + off + 3*TILE_B,          Wl + (size_t)(bn + gr)      * GK + k0 + gc);
        CP_ASYNC16(sP0 + off + 3*TILE_B + 64*80,  Wl + (size_t)(bn + gr + 64) * GK + k0 + gc);
        CP_COMMIT();
    };

    const uint32_t a_off = (uint32_t)(wm * 64 + (lid & 15)) * 80 + ((lid >> 4) << 4);
    const uint32_t b_off = (uint32_t)(wn * 32 + ((lid >> 4) << 3) + (lid & 7)) * 80
                         + (((lid >> 3) & 1) << 4);

    issue(0); issue(1);

    for (int i = 0; i < NK0; i++) {
        if (i < NK0 - 1) CP_WAIT1(); else CP_WAIT0();
        __syncthreads();

        const uint32_t off = (uint32_t)(i & 1) * STAGE_B;
        const uint32_t ab  = sb + off + a_off;              // Ah
        const uint32_t bb  = sb + off + 2*TILE_B + b_off;   // Wh
#pragma unroll
        for (int k16 = 0; k16 < 2; k16++) {
            uint32_t ah[4][4], whf[4][2];
#pragma unroll
            for (int mi = 0; mi < 4; mi++)
                LDSM_X4(ah[mi][0], ah[mi][1], ah[mi][2], ah[mi][3],
                        ab + mi * (16 * 80) + k16 * 32);
            LDSM_X4(whf[0][0], whf[0][1], whf[1][0], whf[1][1], bb + k16 * 32);
            LDSM_X4(whf[2][0], whf[2][1], whf[3][0], whf[3][1],
                    bb + 16 * 80 + k16 * 32);
            // pass 1: Ah * Wh
#pragma unroll
            for (int mi = 0; mi < 4; mi++)
#pragma unroll
                for (int ni = 0; ni < 4; ni++)
                    MMA16816(acc[mi][ni], ah[mi][0], ah[mi][1], ah[mi][2], ah[mi][3],
                             whf[ni][0], whf[ni][1]);
            // pass 2: Ah * Wl (reuse ah)
            {
                uint32_t wlf[4][2];
                LDSM_X4(wlf[0][0], wlf[0][1], wlf[1][0], wlf[1][1],
                        bb + TILE_B + k16 * 32);
                LDSM_X4(wlf[2][0], wlf[2][1], wlf[3][0], wlf[3][1],
                        bb + TILE_B + 16 * 80 + k16 * 32);
#pragma unroll
                for (int mi = 0; mi < 4; mi++)
#pragma unroll
                    for (int ni = 0; ni < 4; ni++)
                        MMA16816(acc[mi][ni], ah[mi][0], ah[mi][1], ah[mi][2], ah[mi][3],
                                 wlf[ni][0], wlf[ni][1]);
            }
            // pass 3: Al * Wh (reuse whf)
            {
                uint32_t al[4][4];
#pragma unroll
                for (int mi = 0; mi < 4; mi++)
                    LDSM_X4(al[mi][0], al[mi][1], al[mi][2], al[mi][3],
                            ab + TILE_B + mi * (16 * 80) + k16 * 32);
#pragma unroll
                for (int mi = 0; mi < 4; mi++)
#pragma unroll
                    for (int ni = 0; ni < 4; ni++)
                        MMA16816(acc[mi][ni], al[mi][0], al[mi][1], al[mi][2], al[mi][3],
                                 whf[ni][0], whf[ni][1]);
            }
        }
        __syncthreads();
        if (i + 2 < NK0) issue(i + 2);
    }

    const int g   = lid >> 2;
    const int tg2 = (lid & 3) * 2;

    if (mode == 2) {
        // ---- stage fp32 tile (+bias) in smem, then rope + scale + split ----
        float* sf = (float*)smem;
        __syncthreads();
#pragma unroll
        for (int ni = 0; ni < 4; ni++) {
            const int col = wn * 32 + ni * 8 + tg2;
            const float b0 = bias[bn + col], b1 = bias[bn + col + 1];
#pragma unroll
            for (int mi = 0; mi < 4; mi++) {
                const int row = wm * 64 + mi * 16 + g;
                sf[row * 132 + col]           = acc[mi][ni][0] + b0;
                sf[row * 132 + col + 1]       = acc[mi][ni][1] + b1;
                sf[(row + 8) * 132 + col]     = acc[mi][ni][2] + b0;
                sf[(row + 8) * 132 + col + 1] = acc[mi][ni][3] + b1;
            }
        }
        __syncthreads();
#pragma unroll
        for (int p = 0; p < 32; p++) {
            const int idx = tid + p * 256;     // 0..8191
            const int r = idx >> 6, i = idx & 63;
            const int rowg = bm + r;
            const int s = rowg & (Sn - 1);
            const float c  = g_ct[(s << 6) | i];
            const float sv = g_st[(s << 6) | i];
            const float v1 = sf[r * 132 + i];
            const float v2 = sf[r * 132 + i + 64];
            const float y1 = (v1 * c - v2 * sv) * scale;
            const float y2 = (v2 * c + v1 * sv) * scale;
            const __nv_bfloat16 h1 = __float2bfloat16(y1);
            const __nv_bfloat16 h2 = __float2bfloat16(y2);
            const size_t o = (size_t)rowg * Dn + bn + i;
            Ch[o]      = h1;
            Ch[o + 64] = h2;
            Cl[o]      = __float2bfloat16(y1 - __bfloat162float(h1));
            Cl[o + 64] = __float2bfloat16(y2 - __bfloat162float(h2));
        }
        return;
    }

#pragma unroll
    for (int ni = 0; ni < 4; ni++) {
        const int col = bn + wn * 32 + ni * 8 + tg2;
        const float b0 = bias[col], b1 = bias[col + 1];
#pragma unroll
        for (int mi = 0; mi < 4; mi++) {
            const size_t row = (size_t)(bm + wm * 64 + mi * 16 + g);
            float v00 = acc[mi][ni][0] + b0, v01 = acc[mi][ni][1] + b1;
            float v10 = acc[mi][ni][2] + b0, v11 = acc[mi][ni][3] + b1;
            if (mode == 1) {
                __nv_bfloat162 h0 = split_hi2(v00, v01);
                __nv_bfloat162 h1 = split_hi2(v10, v11);
                *(__nv_bfloat162*)(Ch + row * Dn + col)       = h0;
                *(__nv_bfloat162*)(Ch + (row + 8) * Dn + col) = h1;
                *(__nv_bfloat162*)(Cl + row * Dn + col)       = split_lo2(v00, v01, h0);
                *(__nv_bfloat162*)(Cl + (row + 8) * Dn + col) = split_lo2(v10, v11, h1);
            } else {
                *(float2*)(C + row * Dn + col)       = make_float2(v00, v01);
                *(float2*)(C + (row + 8) * Dn + col) = make_float2(v10, v11);
            }
        }
    }
}

// ---------------------------------------------------------------------------
// Flash attention on tensor cores; softmax in exp2 domain (log2e folded into
// Q's epilogue scale). Br=128, Bc=64, 8 warps. P stays in registers.
// ---------------------------------------------------------------------------
#define QROW    272
#define SQL_OFF 34816            // 128*272
#define SKV_OFF 69632
#define KL_OFF  17408            // 64*272
#define VH_OFF  34816
#define VL_OFF  52224
#define FAB_SZ  69632            // Kh+Kl+Vh+Vl per buffer
#define FAM_SMEM (SKV_OFF + 2*FAB_SZ)   // 208896

__global__ __launch_bounds__(256, 1) void flash_attn_mma(
    const __nv_bfloat16* __restrict__ Qh, const __nv_bfloat16* __restrict__ Ql,
    const __nv_bfloat16* __restrict__ Kh, const __nv_bfloat16* __restrict__ Kl,
    const __nv_bfloat16* __restrict__ Vh, const __nv_bfloat16* __restrict__ Vl,
    __nv_bfloat16* __restrict__ Ohi, __nv_bfloat16* __restrict__ Olo)
{
    extern __shared__ __align__(16) char sm[];
    const uint32_t sb = smem_u32(sm);
    const int tid = threadIdx.x, lid = tid & 31, wid = tid >> 5;
    const int qt = blockIdx.x;
    const int bh = blockIdx.y;
    const int b = bh >> 4, h = bh & 15;

    {
        const size_t qrow0 = (size_t)(b * Sn + qt * 128);
#pragma unroll
        for (int p = 0; p < 8; p++) {
            int idx = tid + p * 256;
            int r = idx >> 4, c = idx & 15;
            size_t g = (qrow0 + r) * Dn + h * DHn + c * 8;
            uint32_t so = (uint32_t)(r * QROW + c * 16);
            CP_ASYNC16(sb + so,           Qh + g);
            CP_ASYNC16(sb + SQL_OFF + so, Ql + g);
        }
    }

    auto issue = [&](int j) {
        const uint32_t kb = sb + SKV_OFF + (uint32_t)(j & 1) * FAB_SZ;
        const size_t krow0 = (size_t)(b * Sn + j * 64);
#pragma unroll
        for (int p = 0; p < 4; p++) {
            int idx = tid + p * 256;
            int r = idx >> 4, c = idx & 15;
            size_t g = (krow0 + r) * Dn + h * DHn + c * 8;
            uint32_t so = (uint32_t)(r * QROW + c * 16);
            CP_ASYNC16(kb + so,          Kh + g);
            CP_ASYNC16(kb + KL_OFF + so, Kl + g);
            CP_ASYNC16(kb + VH_OFF + so, Vh + g);
            CP_ASYNC16(kb + VL_OFF + so, Vl + g);
        }
        CP_COMMIT();
    };
    issue(0);

    const uint32_t aoff = (uint32_t)((wid * 16 + (lid & 15)) * QROW + ((lid >> 4) << 4));
    const uint32_t boff = (uint32_t)(((((lid >> 4) << 3) + (lid & 7))) * QROW
                                     + (((lid >> 3) & 1) << 4));
    const uint32_t voff = (uint32_t)((((lid & 7) + (((lid >> 3) & 1) << 3))) * QROW
                                     + ((lid >> 4) << 4));

    float oacc[16][4];
#pragma unroll
    for (int i = 0; i < 16; i++)
#pragma unroll
        for (int j = 0; j < 4; j++) oacc[i][j] = 0.f;
    float m0 = -1e30f, m1 = -1e30f, l0 = 0.f, l1 = 0.f;

    for (int j = 0; j < Sn / 64; j++) {
        CP_WAIT0();
        __syncthreads();
        if (j + 1 < Sn / 64) issue(j + 1);
        const uint32_t kb = sb + SKV_OFF + (uint32_t)(j & 1) * FAB_SZ;

        float sacc[8][4];
#pragma unroll
        for (int t = 0; t < 8; t++)
#pragma unroll
            for (int c = 0; c < 4; c++) sacc[t][c] = 0.f;

#pragma unroll
        for (int t = 0; t < 8; t++) {
            uint32_t ah[4], al[4];
            LDSM_X4(ah[0], ah[1], ah[2], ah[3], sb + aoff + t * 32);
            LDSM_X4(al[0], al[1], al[2], al[3], sb + SQL_OFF + aoff + t * 32);
#pragma unroll
            for (int nj = 0; nj < 4; nj++) {
                uint32_t bh4[4], bl4[4];
                uint32_t bad = kb + boff + nj * (16 * QROW) + t * 32;
                LDSM_X4(bh4[0], bh4[1], bh4[2], bh4[3], bad);
                MMA16816(sacc[2*nj],   ah[0], ah[1], ah[2], ah[3], bh4[0], bh4[1]);
                MMA16816(sacc[2*nj+1], ah[0], ah[1], ah[2], ah[3], bh4[2], bh4[3]);
                MMA16816(sacc[2*nj],   al[0], al[1], al[2], al[3], bh4[0], bh4[1]);
                MMA16816(sacc[2*nj+1], al[0], al[1], al[2], al[3], bh4[2], bh4[3]);
                LDSM_X4(bl4[0], bl4[1], bl4[2], bl4[3], bad + KL_OFF);
                MMA16816(sacc[2*nj],   ah[0], ah[1], ah[2], ah[3], bl4[0], bl4[1]);
                MMA16816(sacc[2*nj+1], ah[0], ah[1], ah[2], ah[3], bl4[2], bl4[3]);
            }
        }

        float mx0 = sacc[0][0], mx1 = sacc[0][2];
#pragma unroll
        for (int t = 0; t < 8; t++) {
            mx0 = fmaxf(mx0, fmaxf(sacc[t][0], sacc[t][1]));
            mx1 = fmaxf(mx1, fmaxf(sacc[t][2], sacc[t][3]));
        }
        mx0 = fmaxf(mx0, __shfl_xor_sync(0xffffffffu, mx0, 1));
        mx0 = fmaxf(mx0, __shfl_xor_sync(0xffffffffu, mx0, 2));
        mx1 = fmaxf(mx1, __shfl_xor_sync(0xffffffffu, mx1, 1));
        mx1 = fmaxf(mx1, __shfl_xor_sync(0xffffffffu, mx1, 2));

        const float mn0 = fmaxf(m0, mx0);
        const float mn1 = fmaxf(m1, mx1);
        const float cor0 = ex2f(m0 - mn0);
        const float cor1 = ex2f(m1 - mn1);
        m0 = mn0; m1 = mn1;
#pragma unroll
        for (int nt = 0; nt < 16; nt++) {
            oacc[nt][0] *= cor0; oacc[nt][1] *= cor0;
            oacc[nt][2] *= cor1; oacc[nt][3] *= cor1;
        }

        uint32_t pf[4][4], pl[4][4];
        float s0 = 0.f, s1 = 0.f;
#pragma unroll
        for (int jt = 0; jt < 8; jt++) {
            float p0 = ex2f(sacc[jt][0] - mn0);
            float p1 = ex2f(sacc[jt][1] - mn0);
            float p2 = ex2f(sacc[jt][2] - mn1);
            float p3 = ex2f(sacc[jt][3] - mn1);
            s0 += p0 + p1; s1 += p2 + p3;
            __nv_bfloat162 hA = split_hi2(p0, p1);
            __nv_bfloat162 hB = split_hi2(p2, p3);
            __nv_bfloat162 lA = split_lo2(p0, p1, hA);
            __nv_bfloat162 lB = split_lo2(p2, p3, hB);
            const int t = jt >> 1, o = (jt & 1) * 2;
            pf[t][o]     = *(uint32_t*)&hA;
            pf[t][o + 1] = *(uint32_t*)&hB;
            pl[t][o]     = *(uint32_t*)&lA;
            pl[t][o + 1] = *(uint32_t*)&lB;
        }
        s0 += __shfl_xor_sync(0xffffffffu, s0, 1);
        s0 += __shfl_xor_sync(0xffffffffu, s0, 2);
        s1 += __shfl_xor_sync(0xffffffffu, s1, 1);
        s1 += __shfl_xor_sync(0xffffffffu, s1, 2);
        l0 = l0 * cor0 + s0;
        l1 = l1 * cor1 + s1;

#pragma unroll
        for (int t = 0; t < 4; t++) {
#pragma unroll
            for (int p = 0; p < 8; p++) {
                uint32_t vh4[4], vl4[4];
                uint32_t vad = kb + VH_OFF + voff + t * (16 * QROW) + p * 32;
                LDSM_X4T(vh4[0], vh4[1], vh4[2], vh4[3], vad);
                MMA16816(oacc[2*p],   pf[t][0], pf[t][1], pf[t][2], pf[t][3], vh4[0], vh4[1]);
                MMA16816(oacc[2*p+1], pf[t][0], pf[t][1], pf[t][2], pf[t][3], vh4[2], vh4[3]);
                MMA16816(oacc[2*p],   pl[t][0], pl[t][1], pl[t][2], pl[t][3], vh4[0], vh4[1]);
                MMA16816(oacc[2*p+1], pl[t][0], pl[t][1], pl[t][2], pl[t][3], vh4[2], vh4[3]);
                LDSM_X4T(vl4[0], vl4[1], vl4[2], vl4[3], vad + KL_OFF);
                MMA16816(oacc[2*p],   pf[t][0], pf[t][1], pf[t][2], pf[t][3], vl4[0], vl4[1]);
                MMA16816(oacc[2*p+1], pf[t][0], pf[t][1], pf[t][2], pf[t][3], vl4[2], vl4[3]);
            }
        }
    }

    const float i0 = 1.f / l0, i1 = 1.f / l1;
    const int g = lid >> 2, tg2 = (lid & 3) * 2;
    const size_t row = (size_t)(b * Sn + qt * 128 + wid * 16 + g);
#pragma unroll
    for (int nt = 0; nt < 16; nt++) {
        const int col = h * DHn + nt * 8 + tg2;
        float v00 = oacc[nt][0] * i0, v01 = oacc[nt][1] * i0;
        float v10 = oacc[nt][2] * i1, v11 = oacc[nt][3] * i1;
        __nv_bfloat162 h0 = split_hi2(v00, v01);
        __nv_bfloat162 h1 = split_hi2(v10, v11);
        *(__nv_bfloat162*)(Ohi + row * Dn + col)       = h0;
        *(__nv_bfloat162*)(Ohi + (row + 8) * Dn + col) = h1;
        *(__nv_bfloat162*)(Olo + row * Dn + col)       = split_lo2(v00, v01, h0);
        *(__nv_bfloat162*)(Olo + (row + 8) * Dn + col) = split_lo2(v10, v11, h1);
    }
}

// ---------------------------------------------------------------------------
// Launch
// ---------------------------------------------------------------------------
extern "C" void kernel_launch(void* const* d_in, const int* in_sizes, int n_in,
                              void* d_out, int out_size)
{
    const float* x     = (const float*)d_in[0];
    const float* q_w   = (const float*)d_in[1];
    const float* k_w   = (const float*)d_in[2];
    const float* v_w   = (const float*)d_in[3];
    const float* q_b   = (const float*)d_in[4];
    const float* k_b   = (const float*)d_in[5];
    const float* v_b   = (const float*)d_in[6];
    const float* out_w = (const float*)d_in[7];
    const float* out_b = (const float*)d_in[8];
    float* out = (float*)d_out;

    __nv_bfloat16 *xh, *xl, *Vh, *Vl, *Qh, *Ql, *Kh, *Kl;
    __nv_bfloat16 *qwh, *qwl, *kwh, *kwl, *vwh, *vwl, *owh, *owl;
    cudaGetSymbolAddress((void**)&xh,  g_xh);  cudaGetSymbolAddress((void**)&xl,  g_xl);
    cudaGetSymbolAddress((void**)&Vh,  g_Vh);  cudaGetSymbolAddress((void**)&Vl,  g_Vl);
    cudaGetSymbolAddress((void**)&Qh,  g_Qh);  cudaGetSymbolAddress((void**)&Ql,  g_Ql);
    cudaGetSymbolAddress((void**)&Kh,  g_Kh);  cudaGetSymbolAddress((void**)&Kl,  g_Kl);
    cudaGetSymbolAddress((void**)&qwh, g_qwh); cudaGetSymbolAddress((void**)&qwl, g_qwl);
    cudaGetSymbolAddress((void**)&kwh, g_kwh); cudaGetSymbolAddress((void**)&kwl, g_kwl);
    cudaGetSymbolAddress((void**)&vwh, g_vwh); cudaGetSymbolAddress((void**)&vwl, g_vwl);
    cudaGetSymbolAddress((void**)&owh, g_owh); cudaGetSymbolAddress((void**)&owl, g_owl);

    cudaFuncSetAttribute(gemm_mma,
                         cudaFuncAttributeMaxDynamicSharedMemorySize, GEMM_SMEM);
    cudaFuncSetAttribute(flash_attn_mma,
                         cudaFuncAttributeMaxDynamicSharedMemorySize, FAM_SMEM);

    const int nx4 = Mn * Dn / 4;
    const int nw4 = Dn * Dn / 4;

    // x split + fused 4-weight split
    split_bf16_kernel<<<(nx4 + 255) / 256, 256>>>(x, xh, xl, nx4);
    {
        Split4Args sa;
        sa.src[0] = q_w;   sa.hi[0] = qwh; sa.lo[0] = qwl;
        sa.src[1] = k_w;   sa.hi[1] = kwh; sa.lo[1] = kwl;
        sa.src[2] = v_w;   sa.hi[2] = vwh; sa.lo[2] = vwl;
        sa.src[3] = out_w; sa.hi[3] = owh; sa.lo[3] = owl;
        split4_kernel<<<dim3((nw4 + 255) / 256, 4), 256>>>(sa, nw4);
    }

    rope_table_kernel<<<dim3(64, Sn / 256), 256>>>();

    // merged QKV GEMM: z=0 Q (rope + scale*log2e), z=1 K (rope), z=2 V (split)
    {
        GemmArgs ga;
        ga.Wh[0] = qwh; ga.Wl[0] = qwl; ga.bias[0] = q_b;
        ga.C[0] = nullptr; ga.Ch[0] = Qh; ga.Cl[0] = Ql;
        ga.scale[0] = 0.12751742883892154f;   // (1/sqrt(128)) * log2(e)
        ga.mode[0] = 2;
        ga.Wh[1] = kwh; ga.Wl[1] = kwl; ga.bias[1] = k_b;
        ga.C[1] = nullptr; ga.Ch[1] = Kh; ga.Cl[1] = Kl;
        ga.scale[1] = 1.0f;
        ga.mode[1] = 2;
        ga.Wh[2] = vwh; ga.Wl[2] = vwl; ga.bias[2] = v_b;
        ga.C[2] = nullptr; ga.Ch[2] = Vh; ga.Cl[2] = Vl;
        ga.scale[2] = 1.0f;
        ga.mode[2] = 1;
        gemm_mma<<<dim3(Dn / 128, Mn / 128, 3), 256, GEMM_SMEM>>>(xh, xl, ga);
    }

    flash_attn_mma<<<dim3(Sn / 128, Bn * Hn), 256, FAM_SMEM>>>(
        Qh, Ql, Kh, Kl, Vh, Vl, xh, xl);

    // output projection (O splits live in xh/xl)
    {
        GemmArgs ga;
        ga.Wh[0] = owh; ga.Wl[0] = owl; ga.bias[0] = out_b;
        ga.C[0] = out; ga.Ch[0] = nullptr; ga.Cl[0] = nullptr;
        ga.scale[0] = 1.0f;
        ga.mode[0] = 0;
        // unused slots
        ga.Wh[1] = ga.Wh[2] = owh; ga.Wl[1] = ga.Wl[2] = owl;
        ga.bias[1] = ga.bias[2] = out_b;
        ga.C[1] = ga.C[2] = nullptr;
        ga.Ch[1] = ga.Ch[2] = nullptr; ga.Cl[1] = ga.Cl[2] = nullptr;
        ga.scale[1] = ga.scale[2] = 1.0f;
        ga.mode[1] = ga.mode[2] = 0;
        gemm_mma<<<dim3(Dn / 128, Mn / 128, 1), 256, GEMM_SMEM>>>(xh, xl, ga);
    }
}

// round 15
// speedup vs baseline: 1.4868x; 1.4868x over previous
#include <cuda_runtime.h>
#include <cuda_bf16.h>
#include <cstdint>
#include <math.h>

// Problem constants
#define Bn  2
#define Sn  2048
#define Dn  2048
#define Hn  16
#define DHn 128
#define Mn  (Bn*Sn)          // 4096 rows for all GEMMs

// ---------------------------------------------------------------------------
// Scratch (no allocation allowed -> __device__ globals)
// ---------------------------------------------------------------------------
__device__ float g_ct[Sn*64];
__device__ float g_st[Sn*64];

// bf16 split copies
__device__ __nv_bfloat16 g_xh[(size_t)Mn*Dn],  g_xl[(size_t)Mn*Dn];   // x splits, later O splits
__device__ __nv_bfloat16 g_Vh[(size_t)Mn*Dn],  g_Vl[(size_t)Mn*Dn];
__device__ __nv_bfloat16 g_Qh[(size_t)Mn*Dn],  g_Ql[(size_t)Mn*Dn];
__device__ __nv_bfloat16 g_Kh[(size_t)Mn*Dn],  g_Kl[(size_t)Mn*Dn];
__device__ __nv_bfloat16 g_qwh[(size_t)Dn*Dn], g_qwl[(size_t)Dn*Dn];
__device__ __nv_bfloat16 g_kwh[(size_t)Dn*Dn], g_kwl[(size_t)Dn*Dn];
__device__ __nv_bfloat16 g_vwh[(size_t)Dn*Dn], g_vwl[(size_t)Dn*Dn];
__device__ __nv_bfloat16 g_owh[(size_t)Dn*Dn], g_owl[(size_t)Dn*Dn];

__device__ __forceinline__ uint32_t smem_u32(const void* p) {
    uint32_t a;
    asm("{ .reg .u64 t; cvta.to.shared.u64 t, %1; cvt.u32.u64 %0, t; }"
        : "=r"(a) : "l"(p));
    return a;
}

#define CP_ASYNC16(smem_addr, gptr) \
    asm volatile("cp.async.cg.shared.global [%0], [%1], 16;" \
                 :: "r"(smem_addr), "l"(gptr) : "memory")
#define CP_COMMIT()  asm volatile("cp.async.commit_group;" ::: "memory")
#define CP_WAIT1()   asm volatile("cp.async.wait_group 1;"  ::: "memory")
#define CP_WAIT0()   asm volatile("cp.async.wait_group 0;"  ::: "memory")

#define LDSM_X4(r0,r1,r2,r3, addr) \
    asm volatile("ldmatrix.sync.aligned.m8n8.x4.shared.b16 {%0,%1,%2,%3}, [%4];" \
        : "=r"(r0),"=r"(r1),"=r"(r2),"=r"(r3) : "r"(addr))
#define LDSM_X4T(r0,r1,r2,r3, addr) \
    asm volatile("ldmatrix.sync.aligned.m8n8.x4.trans.shared.b16 {%0,%1,%2,%3}, [%4];" \
        : "=r"(r0),"=r"(r1),"=r"(r2),"=r"(r3) : "r"(addr))
#define MMA16816(d, a0,a1,a2,a3, b0,b1) \
    asm volatile("mma.sync.aligned.m16n8k16.row.col.f32.bf16.bf16.f32 " \
        "{%0,%1,%2,%3}, {%4,%5,%6,%7}, {%8,%9}, {%0,%1,%2,%3};" \
        : "+f"((d)[0]),"+f"((d)[1]),"+f"((d)[2]),"+f"((d)[3]) \
        : "r"(a0),"r"(a1),"r"(a2),"r"(a3), "r"(b0),"r"(b1))

__device__ __forceinline__ float ex2f(float x) {
    float r;
    asm("ex2.approx.ftz.f32 %0, %1;" : "=f"(r) : "f"(x));
    return r;
}

__device__ __forceinline__ __nv_bfloat162 split_hi2(float a, float b) {
    __nv_bfloat162 t;
    t.x = __float2bfloat16(a);
    t.y = __float2bfloat16(b);
    return t;
}
__device__ __forceinline__ __nv_bfloat162 split_lo2(float a, float b,
                                                    __nv_bfloat162 h) {
    __nv_bfloat162 t;
    t.x = __float2bfloat16(a - __bfloat162float(h.x));
    t.y = __float2bfloat16(b - __bfloat162float(h.y));
    return t;
}

// ---------------------------------------------------------------------------
// bf16 split conversion: hi = bf16(v), lo = bf16(v - hi)
// ---------------------------------------------------------------------------
__global__ void split_bf16_kernel(const float* __restrict__ src,
                                  __nv_bfloat16* __restrict__ hi,
                                  __nv_bfloat16* __restrict__ lo, int n4)
{
    int i = blockIdx.x * blockDim.x + threadIdx.x;
    if (i >= n4) return;
    float4 v = ((const float4*)src)[i];
    __nv_bfloat162 h0 = split_hi2(v.x, v.y);
    __nv_bfloat162 h1 = split_hi2(v.z, v.w);
    ((__nv_bfloat162*)hi)[i*2]   = h0;
    ((__nv_bfloat162*)hi)[i*2+1] = h1;
    ((__nv_bfloat162*)lo)[i*2]   = split_lo2(v.x, v.y, h0);
    ((__nv_bfloat162*)lo)[i*2+1] = split_lo2(v.z, v.w, h1);
}

// ---------------------------------------------------------------------------
// RoPE cos/sin table
// ---------------------------------------------------------------------------
__global__ void rope_table_kernel()
{
    __shared__ double inv_sh;
    const int i = blockIdx.x;                       // 0..63
    const int s = blockIdx.y * 256 + threadIdx.x;   // 0..2047
    if (threadIdx.x == 0)
        inv_sh = exp((double)(-2 * i) * (9.210340371976182736 / 128.0));
    __syncthreads();
    double ang = (double)s * inv_sh;
    double k   = floor(ang * 0.15915494309189533577 + 0.5);  // 1/(2pi)
    double red = ang - k * 6.2831853071795864769;
    float rf = (float)red;
    g_ct[(s << 6) | i] = cosf(rf);
    g_st[(s << 6) | i] = sinf(rf);
}

// ---------------------------------------------------------------------------
// Split-bf16 GEMM, 128x128 tile, k0-grouped 3-pass structure (R10-proven).
// Per k0 chunk the stage holds Ah|Al|Wh|Wl (40KB); fragments are loaded once
// and reused across the 3 mma passes (AhWh, AhWl, AlWh). 2 stages, 2 CTA/SM.
// mode 0: fp32 out. mode 1: bf16 hi/lo split out. mode 2: rope+scale+split.
// ---------------------------------------------------------------------------
#define GK       2048
#define NK0      64                // 64 chunks of BK=32
#define TILE_B   10240             // 128 rows * 80B
#define STAGE_B  (4*TILE_B)        // Ah|Al|Wh|Wl = 40960
#define GSTAGES  2
#define GEMM_SMEM (GSTAGES*STAGE_B)   // 81920

__global__ __launch_bounds__(256, 2) void gemm_mma(
    const __nv_bfloat16* __restrict__ Ah, const __nv_bfloat16* __restrict__ Al,
    const __nv_bfloat16* __restrict__ Wh, const __nv_bfloat16* __restrict__ Wl,
    const float* __restrict__ bias, float* __restrict__ C,
    __nv_bfloat16* __restrict__ Ch, __nv_bfloat16* __restrict__ Cl,
    int mode, float scale)
{
    extern __shared__ __align__(16) char smem[];

    const int tid = threadIdx.x;
    const int lid = tid & 31;
    const int wid = tid >> 5;
    const int wm  = wid & 1;
    const int wn  = wid >> 1;
    const int bn  = blockIdx.x * 128;
    const int bm  = blockIdx.y * 128;
    const uint32_t sb = smem_u32(smem);

    const int gr = tid >> 2;
    const int gc = (tid & 3) * 8;

    const uint32_t sP0 = sb + (uint32_t)(gr * 80 + gc * 2);   // row slot in a tile

    float acc[4][4][4];
#pragma unroll
    for (int a = 0; a < 4; a++)
#pragma unroll
        for (int b = 0; b < 4; b++)
#pragma unroll
            for (int c = 0; c < 4; c++) acc[a][b][c] = 0.f;

    auto issue = [&](int ci) {
        const int k0 = ci << 5;
        const uint32_t off = (uint32_t)(ci & 1) * STAGE_B;
        // Ah tile
        CP_ASYNC16(sP0 + off,                     Ah + (size_t)(bm + gr)      * GK + k0 + gc);
        CP_ASYNC16(sP0 + off + 64*80,             Ah + (size_t)(bm + gr + 64) * GK + k0 + gc);
        // Al tile
        CP_ASYNC16(sP0 + off + TILE_B,            Al + (size_t)(bm + gr)      * GK + k0 + gc);
        CP_ASYNC16(sP0 + off + TILE_B + 64*80,    Al + (size_t)(bm + gr + 64) * GK + k0 + gc);
        // Wh tile
        CP_ASYNC16(sP0 + off + 2*TILE_B,          Wh + (size_t)(bn + gr)      * GK + k0 + gc);
        CP_ASYNC16(sP0 + off + 2*TILE_B + 64*80,  Wh + (size_t)(bn + gr + 64) * GK + k0 + gc);
        // Wl tile
        CP_ASYNC16(sP0 + off + 3*TILE_B,          Wl + (size_t)(bn + gr)      * GK + k0 + gc);
        CP_ASYNC16(sP0 + off + 3*TILE_B + 64*80,  Wl + (size_t)(bn + gr + 64) * GK + k0 + gc);
        CP_COMMIT();
    };

    // per-lane ldmatrix bases (within a tile)
    const uint32_t a_off = (uint32_t)(wm * 64 + (lid & 15)) * 80 + ((lid >> 4) << 4);
    const uint32_t b_off = (uint32_t)(wn * 32 + ((lid >> 4) << 3) + (lid & 7)) * 80
                         + (((lid >> 3) & 1) << 4);

    issue(0); issue(1);

    for (int i = 0; i < NK0; i++) {
        if (i < NK0 - 1) CP_WAIT1(); else CP_WAIT0();
        __syncthreads();

        const uint32_t off = (uint32_t)(i & 1) * STAGE_B;
        const uint32_t ab  = sb + off + a_off;              // Ah
        const uint32_t bb  = sb + off + 2*TILE_B + b_off;   // Wh
#pragma unroll
        for (int k16 = 0; k16 < 2; k16++) {
            uint32_t ah[4][4], whf[4][2];
#pragma unroll
            for (int mi = 0; mi < 4; mi++)
                LDSM_X4(ah[mi][0], ah[mi][1], ah[mi][2], ah[mi][3],
                        ab + mi * (16 * 80) + k16 * 32);
            LDSM_X4(whf[0][0], whf[0][1], whf[1][0], whf[1][1], bb + k16 * 32);
            LDSM_X4(whf[2][0], whf[2][1], whf[3][0], whf[3][1],
                    bb + 16 * 80 + k16 * 32);
            // pass 1: Ah * Wh
#pragma unroll
            for (int mi = 0; mi < 4; mi++)
#pragma unroll
                for (int ni = 0; ni < 4; ni++)
                    MMA16816(acc[mi][ni], ah[mi][0], ah[mi][1], ah[mi][2], ah[mi][3],
                             whf[ni][0], whf[ni][1]);
            // pass 2: Ah * Wl (reuse ah)
            {
                uint32_t wlf[4][2];
                LDSM_X4(wlf[0][0], wlf[0][1], wlf[1][0], wlf[1][1],
                        bb + TILE_B + k16 * 32);
                LDSM_X4(wlf[2][0], wlf[2][1], wlf[3][0], wlf[3][1],
                        bb + TILE_B + 16 * 80 + k16 * 32);
#pragma unroll
                for (int mi = 0; mi < 4; mi++)
#pragma unroll
                    for (int ni = 0; ni < 4; ni++)
                        MMA16816(acc[mi][ni], ah[mi][0], ah[mi][1], ah[mi][2], ah[mi][3],
                                 wlf[ni][0], wlf[ni][1]);
            }
            // pass 3: Al * Wh (reuse whf)
            {
                uint32_t al[4][4];
#pragma unroll
                for (int mi = 0; mi < 4; mi++)
                    LDSM_X4(al[mi][0], al[mi][1], al[mi][2], al[mi][3],
                            ab + TILE_B + mi * (16 * 80) + k16 * 32);
#pragma unroll
                for (int mi = 0; mi < 4; mi++)
#pragma unroll
                    for (int ni = 0; ni < 4; ni++)
                        MMA16816(acc[mi][ni], al[mi][0], al[mi][1], al[mi][2], al[mi][3],
                                 whf[ni][0], whf[ni][1]);
            }
        }
        __syncthreads();
        if (i + 2 < NK0) issue(i + 2);
    }

    const int g   = lid >> 2;
    const int tg2 = (lid & 3) * 2;

    if (mode == 2) {
        // ---- stage fp32 tile (+bias) in smem, then rope + scale + split ----
        float* sf = (float*)smem;
        __syncthreads();
#pragma unroll
        for (int ni = 0; ni < 4; ni++) {
            const int col = wn * 32 + ni * 8 + tg2;
            const float b0 = bias[bn + col], b1 = bias[bn + col + 1];
#pragma unroll
            for (int mi = 0; mi < 4; mi++) {
                const int row = wm * 64 + mi * 16 + g;
                sf[row * 132 + col]           = acc[mi][ni][0] + b0;
                sf[row * 132 + col + 1]       = acc[mi][ni][1] + b1;
                sf[(row + 8) * 132 + col]     = acc[mi][ni][2] + b0;
                sf[(row + 8) * 132 + col + 1] = acc[mi][ni][3] + b1;
            }
        }
        __syncthreads();
#pragma unroll
        for (int p = 0; p < 32; p++) {
            const int idx = tid + p * 256;     // 0..8191
            const int r = idx >> 6, i = idx & 63;
            const int rowg = bm + r;
            const int s = rowg & (Sn - 1);
            const float c  = g_ct[(s << 6) | i];
            const float sv = g_st[(s << 6) | i];
            const float v1 = sf[r * 132 + i];
            const float v2 = sf[r * 132 + i + 64];
            const float y1 = (v1 * c - v2 * sv) * scale;
            const float y2 = (v2 * c + v1 * sv) * scale;
            const __nv_bfloat16 h1 = __float2bfloat16(y1);
            const __nv_bfloat16 h2 = __float2bfloat16(y2);
            const size_t o = (size_t)rowg * Dn + bn + i;
            Ch[o]      = h1;
            Ch[o + 64] = h2;
            Cl[o]      = __float2bfloat16(y1 - __bfloat162float(h1));
            Cl[o + 64] = __float2bfloat16(y2 - __bfloat162float(h2));
        }
        return;
    }

#pragma unroll
    for (int ni = 0; ni < 4; ni++) {
        const int col = bn + wn * 32 + ni * 8 + tg2;
        const float b0 = bias[col], b1 = bias[col + 1];
#pragma unroll
        for (int mi = 0; mi < 4; mi++) {
            const size_t row = (size_t)(bm + wm * 64 + mi * 16 + g);
            float v00 = acc[mi][ni][0] + b0, v01 = acc[mi][ni][1] + b1;
            float v10 = acc[mi][ni][2] + b0, v11 = acc[mi][ni][3] + b1;
            if (mode == 1) {
                __nv_bfloat162 h0 = split_hi2(v00, v01);
                __nv_bfloat162 h1 = split_hi2(v10, v11);
                *(__nv_bfloat162*)(Ch + row * Dn + col)       = h0;
                *(__nv_bfloat162*)(Ch + (row + 8) * Dn + col) = h1;
                *(__nv_bfloat162*)(Cl + row * Dn + col)       = split_lo2(v00, v01, h0);
                *(__nv_bfloat162*)(Cl + (row + 8) * Dn + col) = split_lo2(v10, v11, h1);
            } else {
                *(float2*)(C + row * Dn + col)       = make_float2(v00, v01);
                *(float2*)(C + (row + 8) * Dn + col) = make_float2(v10, v11);
            }
        }
    }
}

// ---------------------------------------------------------------------------
// Flash attention on tensor cores; softmax in exp2 domain (log2e folded into
// Q's epilogue scale). Br=128, Bc=64, 8 warps. P stays in registers.
// ---------------------------------------------------------------------------
#define QROW    272
#define SQL_OFF 34816            // 128*272
#define SKV_OFF 69632
#define KL_OFF  17408            // 64*272
#define VH_OFF  34816
#define VL_OFF  52224
#define FAB_SZ  69632            // Kh+Kl+Vh+Vl per buffer
#define FAM_SMEM (SKV_OFF + 2*FAB_SZ)   // 208896

__global__ __launch_bounds__(256, 1) void flash_attn_mma(
    const __nv_bfloat16* __restrict__ Qh, const __nv_bfloat16* __restrict__ Ql,
    const __nv_bfloat16* __restrict__ Kh, const __nv_bfloat16* __restrict__ Kl,
    const __nv_bfloat16* __restrict__ Vh, const __nv_bfloat16* __restrict__ Vl,
    __nv_bfloat16* __restrict__ Ohi, __nv_bfloat16* __restrict__ Olo)
{
    extern __shared__ __align__(16) char sm[];
    const uint32_t sb = smem_u32(sm);
    const int tid = threadIdx.x, lid = tid & 31, wid = tid >> 5;
    const int qt = blockIdx.x;
    const int bh = blockIdx.y;
    const int b = bh >> 4, h = bh & 15;

    {
        const size_t qrow0 = (size_t)(b * Sn + qt * 128);
#pragma unroll
        for (int p = 0; p < 8; p++) {
            int idx = tid + p * 256;
            int r = idx >> 4, c = idx & 15;
            size_t g = (qrow0 + r) * Dn + h * DHn + c * 8;
            uint32_t so = (uint32_t)(r * QROW + c * 16);
            CP_ASYNC16(sb + so,           Qh + g);
            CP_ASYNC16(sb + SQL_OFF + so, Ql + g);
        }
    }

    auto issue = [&](int j) {
        const uint32_t kb = sb + SKV_OFF + (uint32_t)(j & 1) * FAB_SZ;
        const size_t krow0 = (size_t)(b * Sn + j * 64);
#pragma unroll
        for (int p = 0; p < 4; p++) {
            int idx = tid + p * 256;
            int r = idx >> 4, c = idx & 15;
            size_t g = (krow0 + r) * Dn + h * DHn + c * 8;
            uint32_t so = (uint32_t)(r * QROW + c * 16);
            CP_ASYNC16(kb + so,          Kh + g);
            CP_ASYNC16(kb + KL_OFF + so, Kl + g);
            CP_ASYNC16(kb + VH_OFF + so, Vh + g);
            CP_ASYNC16(kb + VL_OFF + so, Vl + g);
        }
        CP_COMMIT();
    };
    issue(0);

    const uint32_t aoff = (uint32_t)((wid * 16 + (lid & 15)) * QROW + ((lid >> 4) << 4));
    const uint32_t boff = (uint32_t)(((((lid >> 4) << 3) + (lid & 7))) * QROW
                                     + (((lid >> 3) & 1) << 4));
    const uint32_t voff = (uint32_t)((((lid & 7) + (((lid >> 3) & 1) << 3))) * QROW
                                     + ((lid >> 4) << 4));

    float oacc[16][4];
#pragma unroll
    for (int i = 0; i < 16; i++)
#pragma unroll
        for (int j = 0; j < 4; j++) oacc[i][j] = 0.f;
    float m0 = -1e30f, m1 = -1e30f, l0 = 0.f, l1 = 0.f;

    for (int j = 0; j < Sn / 64; j++) {
        CP_WAIT0();
        __syncthreads();
        if (j + 1 < Sn / 64) issue(j + 1);
        const uint32_t kb = sb + SKV_OFF + (uint32_t)(j & 1) * FAB_SZ;

        float sacc[8][4];
#pragma unroll
        for (int t = 0; t < 8; t++)
#pragma unroll
            for (int c = 0; c < 4; c++) sacc[t][c] = 0.f;

#pragma unroll
        for (int t = 0; t < 8; t++) {
            uint32_t ah[4], al[4];
            LDSM_X4(ah[0], ah[1], ah[2], ah[3], sb + aoff + t * 32);
            LDSM_X4(al[0], al[1], al[2], al[3], sb + SQL_OFF + aoff + t * 32);
#pragma unroll
            for (int nj = 0; nj < 4; nj++) {
                uint32_t bh4[4], bl4[4];
                uint32_t bad = kb + boff + nj * (16 * QROW) + t * 32;
                LDSM_X4(bh4[0], bh4[1], bh4[2], bh4[3], bad);
                MMA16816(sacc[2*nj],   ah[0], ah[1], ah[2], ah[3], bh4[0], bh4[1]);
                MMA16816(sacc[2*nj+1], ah[0], ah[1], ah[2], ah[3], bh4[2], bh4[3]);
                MMA16816(sacc[2*nj],   al[0], al[1], al[2], al[3], bh4[0], bh4[1]);
                MMA16816(sacc[2*nj+1], al[0], al[1], al[2], al[3], bh4[2], bh4[3]);
                LDSM_X4(bl4[0], bl4[1], bl4[2], bl4[3], bad + KL_OFF);
                MMA16816(sacc[2*nj],   ah[0], ah[1], ah[2], ah[3], bl4[0], bl4[1]);
                MMA16816(sacc[2*nj+1], ah[0], ah[1], ah[2], ah[3], bl4[2], bl4[3]);
            }
        }

        float mx0 = sacc[0][0], mx1 = sacc[0][2];
#pragma unroll
        for (int t = 0; t < 8; t++) {
            mx0 = fmaxf(mx0, fmaxf(sacc[t][0], sacc[t][1]));
            mx1 = fmaxf(mx1, fmaxf(sacc[t][2], sacc[t][3]));
        }
        mx0 = fmaxf(mx0, __shfl_xor_sync(0xffffffffu, mx0, 1));
        mx0 = fmaxf(mx0, __shfl_xor_sync(0xffffffffu, mx0, 2));
        mx1 = fmaxf(mx1, __shfl_xor_sync(0xffffffffu, mx1, 1));
        mx1 = fmaxf(mx1, __shfl_xor_sync(0xffffffffu, mx1, 2));

        const float mn0 = fmaxf(m0, mx0);
        const float mn1 = fmaxf(m1, mx1);
        const float cor0 = ex2f(m0 - mn0);
        const float cor1 = ex2f(m1 - mn1);
        m0 = mn0; m1 = mn1;
#pragma unroll
        for (int nt = 0; nt < 16; nt++) {
            oacc[nt][0] *= cor0; oacc[nt][1] *= cor0;
            oacc[nt][2] *= cor1; oacc[nt][3] *= cor1;
        }

        uint32_t pf[4][4], pl[4][4];
        float s0 = 0.f, s1 = 0.f;
#pragma unroll
        for (int jt = 0; jt < 8; jt++) {
            float p0 = ex2f(sacc[jt][0] - mn0);
            float p1 = ex2f(sacc[jt][1] - mn0);
            float p2 = ex2f(sacc[jt][2] - mn1);
            float p3 = ex2f(sacc[jt][3] - mn1);
            s0 += p0 + p1; s1 += p2 + p3;
            __nv_bfloat162 hA = split_hi2(p0, p1);
            __nv_bfloat162 hB = split_hi2(p2, p3);
            __nv_bfloat162 lA = split_lo2(p0, p1, hA);
            __nv_bfloat162 lB = split_lo2(p2, p3, hB);
            const int t = jt >> 1, o = (jt & 1) * 2;
            pf[t][o]     = *(uint32_t*)&hA;
            pf[t][o + 1] = *(uint32_t*)&hB;
            pl[t][o]     = *(uint32_t*)&lA;
            pl[t][o + 1] = *(uint32_t*)&lB;
        }
        s0 += __shfl_xor_sync(0xffffffffu, s0, 1);
        s0 += __shfl_xor_sync(0xffffffffu, s0, 2);
        s1 += __shfl_xor_sync(0xffffffffu, s1, 1);
        s1 += __shfl_xor_sync(0xffffffffu, s1, 2);
        l0 = l0 * cor0 + s0;
        l1 = l1 * cor1 + s1;

#pragma unroll
        for (int t = 0; t < 4; t++) {
#pragma unroll
            for (int p = 0; p < 8; p++) {
                uint32_t vh4[4], vl4[4];
                uint32_t vad = kb + VH_OFF + voff + t * (16 * QROW) + p * 32;
                LDSM_X4T(vh4[0], vh4[1], vh4[2], vh4[3], vad);
                MMA16816(oacc[2*p],   pf[t][0], pf[t][1], pf[t][2], pf[t][3], vh4[0], vh4[1]);
                MMA16816(oacc[2*p+1], pf[t][0], pf[t][1], pf[t][2], pf[t][3], vh4[2], vh4[3]);
                MMA16816(oacc[2*p],   pl[t][0], pl[t][1], pl[t][2], pl[t][3], vh4[0], vh4[1]);
                MMA16816(oacc[2*p+1], pl[t][0], pl[t][1], pl[t][2], pl[t][3], vh4[2], vh4[3]);
                LDSM_X4T(vl4[0], vl4[1], vl4[2], vl4[3], vad + KL_OFF);
                MMA16816(oacc[2*p],   pf[t][0], pf[t][1], pf[t][2], pf[t][3], vl4[0], vl4[1]);
                MMA16816(oacc[2*p+1], pf[t][0], pf[t][1], pf[t][2], pf[t][3], vl4[2], vl4[3]);
            }
        }
    }

    const float i0 = 1.f / l0, i1 = 1.f / l1;
    const int g = lid >> 2, tg2 = (lid & 3) * 2;
    const size_t row = (size_t)(b * Sn + qt * 128 + wid * 16 + g);
#pragma unroll
    for (int nt = 0; nt < 16; nt++) {
        const int col = h * DHn + nt * 8 + tg2;
        float v00 = oacc[nt][0] * i0, v01 = oacc[nt][1] * i0;
        float v10 = oacc[nt][2] * i1, v11 = oacc[nt][3] * i1;
        __nv_bfloat162 h0 = split_hi2(v00, v01);
        __nv_bfloat162 h1 = split_hi2(v10, v11);
        *(__nv_bfloat162*)(Ohi + row * Dn + col)       = h0;
        *(__nv_bfloat162*)(Ohi + (row + 8) * Dn + col) = h1;
        *(__nv_bfloat162*)(Olo + row * Dn + col)       = split_lo2(v00, v01, h0);
        *(__nv_bfloat162*)(Olo + (row + 8) * Dn + col) = split_lo2(v10, v11, h1);
    }
}

// ---------------------------------------------------------------------------
// Launch
// ---------------------------------------------------------------------------
extern "C" void kernel_launch(void* const* d_in, const int* in_sizes, int n_in,
                              void* d_out, int out_size)
{
    const float* x     = (const float*)d_in[0];
    const float* q_w   = (const float*)d_in[1];
    const float* k_w   = (const float*)d_in[2];
    const float* v_w   = (const float*)d_in[3];
    const float* q_b   = (const float*)d_in[4];
    const float* k_b   = (const float*)d_in[5];
    const float* v_b   = (const float*)d_in[6];
    const float* out_w = (const float*)d_in[7];
    const float* out_b = (const float*)d_in[8];
    float* out = (float*)d_out;

    __nv_bfloat16 *xh, *xl, *Vh, *Vl, *Qh, *Ql, *Kh, *Kl;
    __nv_bfloat16 *qwh, *qwl, *kwh, *kwl, *vwh, *vwl, *owh, *owl;
    cudaGetSymbolAddress((void**)&xh,  g_xh);  cudaGetSymbolAddress((void**)&xl,  g_xl);
    cudaGetSymbolAddress((void**)&Vh,  g_Vh);  cudaGetSymbolAddress((void**)&Vl,  g_Vl);
    cudaGetSymbolAddress((void**)&Qh,  g_Qh);  cudaGetSymbolAddress((void**)&Ql,  g_Ql);
    cudaGetSymbolAddress((void**)&Kh,  g_Kh);  cudaGetSymbolAddress((void**)&Kl,  g_Kl);
    cudaGetSymbolAddress((void**)&qwh, g_qwh); cudaGetSymbolAddress((void**)&qwl, g_qwl);
    cudaGetSymbolAddress((void**)&kwh, g_kwh); cudaGetSymbolAddress((void**)&kwl, g_kwl);
    cudaGetSymbolAddress((void**)&vwh, g_vwh); cudaGetSymbolAddress((void**)&vwl, g_vwl);
    cudaGetSymbolAddress((void**)&owh, g_owh); cudaGetSymbolAddress((void**)&owl, g_owl);

    cudaFuncSetAttribute(gemm_mma,
                         cudaFuncAttributeMaxDynamicSharedMemorySize, GEMM_SMEM);
    cudaFuncSetAttribute(flash_attn_mma,
                         cudaFuncAttributeMaxDynamicSharedMemorySize, FAM_SMEM);

    const int nx4 = Mn * Dn / 4;
    const int nw4 = Dn * Dn / 4;

    split_bf16_kernel<<<(nx4 + 255) / 256, 256>>>(x,     xh,  xl,  nx4);
    split_bf16_kernel<<<(nw4 + 255) / 256, 256>>>(q_w,   qwh, qwl, nw4);
    split_bf16_kernel<<<(nw4 + 255) / 256, 256>>>(k_w,   kwh, kwl, nw4);
    split_bf16_kernel<<<(nw4 + 255) / 256, 256>>>(v_w,   vwh, vwl, nw4);
    split_bf16_kernel<<<(nw4 + 255) / 256, 256>>>(out_w, owh, owl, nw4);

    rope_table_kernel<<<dim3(64, Sn / 256), 256>>>();

    dim3 gg(Dn / 128, Mn / 128);   // (16, 32)
    // Q: rope + (scale*log2e) + split; K: rope + split; V: split
    gemm_mma<<<gg, 256, GEMM_SMEM>>>(xh, xl, qwh, qwl, q_b, nullptr, Qh, Ql,
                                     2, 0.12751742883892154f);
    gemm_mma<<<gg, 256, GEMM_SMEM>>>(xh, xl, kwh, kwl, k_b, nullptr, Kh, Kl,
                                     2, 1.0f);
    gemm_mma<<<gg, 256, GEMM_SMEM>>>(xh, xl, vwh, vwl, v_b, nullptr, Vh, Vl,
                                     1, 1.0f);

    flash_attn_mma<<<dim3(Sn / 128, Bn * Hn), 256, FAM_SMEM>>>(
        Qh, Ql, Kh, Kl, Vh, Vl, xh, xl);

    gemm_mma<<<gg, 256, GEMM_SMEM>>>(xh, xl, owh, owl, out_b, out, nullptr, nullptr,
                                     0, 1.0f);
}